// round 4
// baseline (speedup 1.0000x reference)
#include <cuda_runtime.h>

#define N_NODES 2048
#define NODE_DIM 128
#define HIDDEN 64

// Scratch (no allocation allowed — device globals)
__device__ __align__(16) float g_Wc[NODE_DIM * 2 * HIDDEN];   // [128][128] combined enc->a|b weights
__device__ __align__(16) float g_bc[2 * HIDDEN];              // combined biases (b1 folded into A half)
__device__ __align__(16) float g_AB[N_NODES * 2 * HIDDEN];    // [2048][128]: cols 0..63 = a_i (+bias), 64..127 = b_i

// ---------------------------------------------------------------------------
// P1: combine weights.  Wc[d][h'] = sum_k W_enc[d][k] * W1[sel(k,h')][h]
//     bc[h']            = sum_k b_enc[k] * W1[...] (+ b1 for A half)
// ---------------------------------------------------------------------------
__global__ void prep_weights(const float* __restrict__ W_enc,
                             const float* __restrict__ b_enc,
                             const float* __restrict__ W1,
                             const float* __restrict__ b1)
{
    if (blockIdx.x < 64) {
        int out = blockIdx.x * 256 + threadIdx.x;       // 0..16383
        int d  = out >> 7;
        int hp = out & 127;
        int h    = (hp < HIDDEN) ? hp : hp - HIDDEN;
        int koff = (hp < HIDDEN) ? 0  : HIDDEN;
        float acc = 0.f;
        #pragma unroll 8
        for (int k = 0; k < HIDDEN; k++)
            acc += W_enc[d * HIDDEN + k] * W1[(koff + k) * HIDDEN + h];
        g_Wc[d * 128 + hp] = acc;
    } else {
        int hp = threadIdx.x;
        if (hp < 128) {
            int h    = (hp < HIDDEN) ? hp : hp - HIDDEN;
            int koff = (hp < HIDDEN) ? 0  : HIDDEN;
            float acc = (hp < HIDDEN) ? b1[hp] : 0.f;
            #pragma unroll 8
            for (int k = 0; k < HIDDEN; k++)
                acc += b_enc[k] * W1[(koff + k) * HIDDEN + h];
            g_bc[hp] = acc;
        }
    }
}

// ---------------------------------------------------------------------------
// P2: AB = X @ Wc + bc     (2048 x 128 x 128 GEMM, f32x2 packed over h)
// grid 256 blocks: bid>>1 = 16-row tile, bid&1 = column half (A or B)
// ---------------------------------------------------------------------------
__global__ __launch_bounds__(256, 2) void prep_AB(const float* __restrict__ X)
{
    __shared__ float Xs[16][NODE_DIM];                      // 8 KB
    __shared__ unsigned long long Ws2[NODE_DIM][32];        // 32 KB (this half's 64 cols as pairs)

    const int t    = threadIdx.x;
    const int half = blockIdx.x & 1;
    const int r0   = (blockIdx.x >> 1) * 16;

    for (int idx = t; idx < NODE_DIM * 32; idx += 256) {
        int d = idx >> 5, p = idx & 31;
        Ws2[d][p] = *(const unsigned long long*)&g_Wc[d * 128 + half * HIDDEN + 2 * p];
    }
    for (int idx = t; idx < 16 * NODE_DIM; idx += 256) {
        int r = idx >> 7, d = idx & 127;
        Xs[r][d] = X[(r0 + r) * NODE_DIM + d];
    }
    __syncthreads();

    const int tx = t & 15;      // column-pair base
    const int ty = t >> 4;      // row
    unsigned long long acc0 = 0ull, acc1 = 0ull;

    #pragma unroll 4
    for (int d = 0; d < NODE_DIM; d++) {
        unsigned xu = __float_as_uint(Xs[ty][d]);
        unsigned long long x2;
        asm("mov.b64 %0, {%1, %2};" : "=l"(x2) : "r"(xu), "r"(xu));
        unsigned long long w0 = Ws2[d][tx];
        unsigned long long w1 = Ws2[d][tx + 16];
        asm("fma.rn.f32x2 %0, %1, %2, %0;" : "+l"(acc0) : "l"(x2), "l"(w0));
        asm("fma.rn.f32x2 %0, %1, %2, %0;" : "+l"(acc1) : "l"(x2), "l"(w1));
    }

    const int row = r0 + ty;
    #pragma unroll
    for (int u = 0; u < 2; u++) {
        unsigned long long a = u ? acc1 : acc0;
        unsigned lo_u, hi_u;
        asm("mov.b64 {%0, %1}, %2;" : "=r"(lo_u), "=r"(hi_u) : "l"(a));
        int hp = half * HIDDEN + 2 * (tx + 16 * u);
        float2 v;
        v.x = __uint_as_float(lo_u) + g_bc[hp];
        v.y = __uint_as_float(hi_u) + g_bc[hp + 1];
        *(float2*)&g_AB[row * 128 + hp] = v;
    }
}

// ---------------------------------------------------------------------------
// Main: out[i][j] = sigmoid( sum_h relu(A[i][h]+B[j][h]) * W2[h] + b2 ), diag=0
// 64x64 tile per block, 256 threads, 4x4 micro-tile, f32x2 packed over h.
// Smem tiles XOR-swizzled: col index (hh ^ (row&31)) -> conflict-free LDS.64.
// ---------------------------------------------------------------------------
__global__ __launch_bounds__(256, 2) void pairwise(const float* __restrict__ W2,
                                                   const float* __restrict__ b2p,
                                                   float* __restrict__ out)
{
    __shared__ unsigned long long As2[64 * 32];   // 16 KB
    __shared__ unsigned long long Bs2[64 * 32];   // 16 KB
    __shared__ unsigned long long w2s[32];

    const int t  = threadIdx.x;
    const int i0 = blockIdx.y * 64;
    const int j0 = blockIdx.x * 64;

    for (int idx = t; idx < 64 * 32; idx += 256) {
        int r = idx >> 5, hh = idx & 31;
        int sc = hh ^ (r & 31);
        As2[r * 32 + sc] = *(const unsigned long long*)&g_AB[(i0 + r) * 128 + 2 * hh];
        Bs2[r * 32 + sc] = *(const unsigned long long*)&g_AB[(j0 + r) * 128 + HIDDEN + 2 * hh];
    }
    if (t < 32) w2s[t] = *(const unsigned long long*)&W2[2 * t];
    __syncthreads();

    const int tx = t & 15;      // j = j0 + tx + 16c
    const int ty = t >> 4;      // i = i0 + ty + 16r

    unsigned long long acc[4][4];
    #pragma unroll
    for (int r = 0; r < 4; r++)
        #pragma unroll
        for (int c = 0; c < 4; c++) acc[r][c] = 0ull;

    #pragma unroll 8
    for (int hh = 0; hh < 32; hh++) {
        const unsigned long long w2 = w2s[hh];
        unsigned long long av[4], bv[4];
        #pragma unroll
        for (int r = 0; r < 4; r++) {
            int i = ty + 16 * r;
            av[r] = As2[i * 32 + (hh ^ (i & 31))];
        }
        #pragma unroll
        for (int c = 0; c < 4; c++) {
            int j = tx + 16 * c;
            bv[c] = Bs2[j * 32 + (hh ^ (j & 31))];
        }
        #pragma unroll
        for (int r = 0; r < 4; r++) {
            #pragma unroll
            for (int c = 0; c < 4; c++) {
                unsigned long long s;
                asm("add.rn.f32x2 %0, %1, %2;" : "=l"(s) : "l"(av[r]), "l"(bv[c]));
                unsigned lo_u, hi_u;
                asm("mov.b64 {%0, %1}, %2;" : "=r"(lo_u), "=r"(hi_u) : "l"(s));
                float lo = fmaxf(__uint_as_float(lo_u), 0.0f);
                float hi = fmaxf(__uint_as_float(hi_u), 0.0f);
                asm("mov.b64 %0, {%1, %2};" : "=l"(s)
                    : "r"(__float_as_uint(lo)), "r"(__float_as_uint(hi)));
                asm("fma.rn.f32x2 %0, %1, %2, %0;" : "+l"(acc[r][c]) : "l"(s), "l"(w2));
            }
        }
    }

    const float bias2 = __ldg(b2p);
    #pragma unroll
    for (int r = 0; r < 4; r++) {
        const int i = i0 + ty + 16 * r;
        #pragma unroll
        for (int c = 0; c < 4; c++) {
            const int j = j0 + tx + 16 * c;
            unsigned lo_u, hi_u;
            asm("mov.b64 {%0, %1}, %2;" : "=r"(lo_u), "=r"(hi_u) : "l"(acc[r][c]));
            float logit = __uint_as_float(lo_u) + __uint_as_float(hi_u) + bias2;
            float T = 1.0f / (1.0f + __expf(-logit));
            out[i * N_NODES + j] = (i == j) ? 0.0f : T;
        }
    }
}

extern "C" void kernel_launch(void* const* d_in, const int* in_sizes, int n_in,
                              void* d_out, int out_size)
{
    const float* X     = (const float*)d_in[0];
    const float* W_enc = (const float*)d_in[1];
    const float* b_enc = (const float*)d_in[2];
    const float* W1    = (const float*)d_in[3];
    const float* b1    = (const float*)d_in[4];
    const float* W2    = (const float*)d_in[5];
    const float* b2    = (const float*)d_in[6];
    float* out = (float*)d_out;

    prep_weights<<<65, 256>>>(W_enc, b_enc, W1, b1);
    prep_AB<<<256, 256>>>(X);
    dim3 grid(N_NODES / 64, N_NODES / 64);
    pairwise<<<grid, 256>>>(W2, b2, out);
}

// round 5
// speedup vs baseline: 1.1298x; 1.1298x over previous
#include <cuda_runtime.h>

typedef unsigned long long ull;

#define N_NODES 2048
#define NODE_DIM 128
#define HIDDEN 64

// Scratch (no allocation allowed — device globals)
__device__ __align__(16) float g_Wc[NODE_DIM * 128];     // combined enc->a|b weights [128][128]
__device__ __align__(16) float g_bc[128];                // combined biases (b1 folded into A half)
__device__ __align__(16) float g_c2[64];                 // 0.5 * W2[h]
__device__ __align__(16) ull   g_ABT[64 * N_NODES];      // [h-pair][node]; pairs 0..31 = A, 32..63 = B
__device__ __align__(16) float g_Sa[N_NODES];            // sum_h (w/2) a_ih  + b2
__device__ __align__(16) float g_Sb[N_NODES];            // sum_h (w/2) b_jh

// ---------------------------------------------------------------------------
// P1: combine weights with smem staging.
//   blocks 0..7: Wc[d][hp] = sum_k W_enc[d][k] * W1[koff+k][h]   (16 d-rows/block)
//   block 8:     bc[hp] (b1 folded into A half) and c2 = 0.5*W2
// ---------------------------------------------------------------------------
__global__ __launch_bounds__(256) void prep_weights(const float* __restrict__ W_enc,
                                                    const float* __restrict__ b_enc,
                                                    const float* __restrict__ W1,
                                                    const float* __restrict__ b1,
                                                    const float* __restrict__ W2)
{
    if (blockIdx.x < 8) {
        __shared__ float W1s[128][68];   // padded
        __shared__ float Wes[16][64];
        const int t = threadIdx.x;
        const int d0 = blockIdx.x * 16;

        for (int idx = t; idx < 128 * 64; idx += 256)
            W1s[idx >> 6][idx & 63] = W1[idx];
        for (int idx = t; idx < 16 * 64; idx += 256)
            Wes[idx >> 6][idx & 63] = W_enc[(d0 + (idx >> 6)) * 64 + (idx & 63)];
        __syncthreads();

        const int dl   = t >> 4;             // local d row 0..15
        const int hp0  = (t & 15) * 8;       // output column base 0..120
        const int h0   = hp0 & 63;
        const int koff = (hp0 < 64) ? 0 : 64;

        float acc[8];
        #pragma unroll
        for (int u = 0; u < 8; u++) acc[u] = 0.f;

        #pragma unroll 4
        for (int k = 0; k < 64; k++) {
            const float we = Wes[dl][k];
            #pragma unroll
            for (int u = 0; u < 8; u++)
                acc[u] += we * W1s[koff + k][h0 + u];
        }
        #pragma unroll
        for (int u = 0; u < 8; u++)
            g_Wc[(d0 + dl) * 128 + hp0 + u] = acc[u];
    } else {
        const int t = threadIdx.x;
        if (t < 128) {
            const int h    = t & 63;
            const int koff = (t < 64) ? 0 : 64;
            float acc = (t < 64) ? b1[t] : 0.f;
            #pragma unroll 8
            for (int k = 0; k < 64; k++)
                acc += b_enc[k] * W1[(koff + k) * 64 + h];
            g_bc[t] = acc;
        } else if (t < 192) {
            g_c2[t - 128] = 0.5f * W2[t - 128];
        }
    }
}

// ---------------------------------------------------------------------------
// P2: AB = X @ Wc + bc, stored TRANSPOSED as g_ABT[pair][node].
// Also computes separable sums Sa/Sb via shuffle-reduce.
// grid 256 blocks: bid>>1 = 16-row tile, bid&1 = column half (A or B)
// ---------------------------------------------------------------------------
__global__ __launch_bounds__(256, 2) void prep_AB(const float* __restrict__ X,
                                                  const float* __restrict__ b2)
{
    __shared__ float Xs[16][NODE_DIM];                      // 8 KB
    __shared__ ull   Ws2[NODE_DIM][32];                     // 32 KB (this half's 64 cols as pairs)

    const int t    = threadIdx.x;
    const int half = blockIdx.x & 1;
    const int r0   = (blockIdx.x >> 1) * 16;

    for (int idx = t; idx < NODE_DIM * 32; idx += 256) {
        int d = idx >> 5, p = idx & 31;
        Ws2[d][p] = *(const ull*)&g_Wc[d * 128 + half * HIDDEN + 2 * p];
    }
    for (int idx = t; idx < 16 * NODE_DIM; idx += 256) {
        int r = idx >> 7, d = idx & 127;
        Xs[r][d] = X[(r0 + r) * NODE_DIM + d];
    }
    __syncthreads();

    const int tx = t & 15;      // column-pair base
    const int ty = t >> 4;      // row
    ull acc0 = 0ull, acc1 = 0ull;

    #pragma unroll 4
    for (int d = 0; d < NODE_DIM; d++) {
        unsigned xu = __float_as_uint(Xs[ty][d]);
        ull x2;
        asm("mov.b64 %0, {%1, %2};" : "=l"(x2) : "r"(xu), "r"(xu));
        ull w0 = Ws2[d][tx];
        ull w1 = Ws2[d][tx + 16];
        asm("fma.rn.f32x2 %0, %1, %2, %0;" : "+l"(acc0) : "l"(x2), "l"(w0));
        asm("fma.rn.f32x2 %0, %1, %2, %0;" : "+l"(acc1) : "l"(x2), "l"(w1));
    }

    const int row = r0 + ty;
    float partial = 0.f;
    #pragma unroll
    for (int u = 0; u < 2; u++) {
        ull a = u ? acc1 : acc0;
        unsigned lo_u, hi_u;
        asm("mov.b64 {%0, %1}, %2;" : "=r"(lo_u), "=r"(hi_u) : "l"(a));
        const int pl = tx + 16 * u;                 // pair index within half 0..31
        const int hp = half * HIDDEN + 2 * pl;
        float vx = __uint_as_float(lo_u) + g_bc[hp];
        float vy = __uint_as_float(hi_u) + g_bc[hp + 1];
        ull pv;
        asm("mov.b64 %0, {%1, %2};" : "=l"(pv)
            : "r"(__float_as_uint(vx)), "r"(__float_as_uint(vy)));
        g_ABT[(half * 32 + pl) * N_NODES + row] = pv;
        partial += vx * g_c2[2 * pl] + vy * g_c2[2 * pl + 1];
    }
    // reduce over the 16 tx lanes of this row-half
    #pragma unroll
    for (int m = 1; m < 16; m <<= 1)
        partial += __shfl_xor_sync(0xffffffffu, partial, m);
    if (tx == 0) {
        if (half == 0) g_Sa[row] = partial + __ldg(b2);
        else           g_Sb[row] = partial;
    }
}

// ---------------------------------------------------------------------------
// Main: logit_ij = Sa_i + Sb_j + sum_h c_h * |a_ih + b_jh|,  out = sigmoid, diag=0
// (uses w*relu(x) = (w/2)x + (w/2)|x|; separable part precomputed)
// 64x64 tile per block, 256 threads, 4x4 micro-tile, pure-b64 inner loop:
// add.rn.f32x2 -> and.b64 (abs) -> fma.rn.f32x2. Smem tiles [hh][node], stride 65
// -> conflict-free LDS.64 with immediate offsets (zero address math).
// ---------------------------------------------------------------------------
__global__ __launch_bounds__(256, 2) void pairwise(float* __restrict__ out)
{
    __shared__ ull  As[32 * 65];     // [hh][i], 16.6 KB
    __shared__ ull  Bs[32 * 65];
    __shared__ ull  w2s[32];         // c = W2/2, packed pairs
    __shared__ float sSa[64], sSb[64];

    const int t  = threadIdx.x;
    const int i0 = blockIdx.y * 64;
    const int j0 = blockIdx.x * 64;

    for (int idx = t; idx < 2048; idx += 256) {
        int hh = idx >> 6, col = idx & 63;
        As[hh * 65 + col] = g_ABT[hh * N_NODES + i0 + col];
        Bs[hh * 65 + col] = g_ABT[(32 + hh) * N_NODES + j0 + col];
    }
    if (t < 32)       w2s[t]       = ((const ull*)g_c2)[t];
    else if (t < 96)  sSa[t - 32]  = g_Sa[i0 + t - 32];
    else if (t < 160) sSb[t - 96]  = g_Sb[j0 + t - 96];
    __syncthreads();

    const int tx = t & 15;      // j = j0 + tx + 16c
    const int ty = t >> 4;      // i = i0 + ty + 16r

    ull acc[4][4];
    #pragma unroll
    for (int r = 0; r < 4; r++)
        #pragma unroll
        for (int c = 0; c < 4; c++) acc[r][c] = 0ull;

    #pragma unroll 1
    for (int hh0 = 0; hh0 < 32; hh0 += 16) {
        #pragma unroll
        for (int k = 0; k < 16; k++) {
            const int hh = hh0 + k;
            const ull w2 = w2s[hh];
            ull av[4], bv[4];
            #pragma unroll
            for (int r = 0; r < 4; r++) av[r] = As[hh * 65 + ty + 16 * r];
            #pragma unroll
            for (int c = 0; c < 4; c++) bv[c] = Bs[hh * 65 + tx + 16 * c];
            #pragma unroll
            for (int r = 0; r < 4; r++) {
                #pragma unroll
                for (int c = 0; c < 4; c++) {
                    ull s;
                    asm("add.rn.f32x2 %0, %1, %2;" : "=l"(s) : "l"(av[r]), "l"(bv[c]));
                    asm("and.b64 %0, %0, 0x7FFFFFFF7FFFFFFF;" : "+l"(s));
                    asm("fma.rn.f32x2 %0, %1, %2, %0;" : "+l"(acc[r][c]) : "l"(s), "l"(w2));
                }
            }
        }
    }

    float Sar[4], Sbc[4];
    #pragma unroll
    for (int r = 0; r < 4; r++) Sar[r] = sSa[ty + 16 * r];
    #pragma unroll
    for (int c = 0; c < 4; c++) Sbc[c] = sSb[tx + 16 * c];

    const bool dd = (i0 == j0) && (tx == ty);

    #pragma unroll
    for (int r = 0; r < 4; r++) {
        float* prow = out + (size_t)(i0 + ty + 16 * r) * N_NODES + j0 + tx;
        #pragma unroll
        for (int c = 0; c < 4; c++) {
            unsigned lo_u, hi_u;
            asm("mov.b64 {%0, %1}, %2;" : "=r"(lo_u), "=r"(hi_u) : "l"(acc[r][c]));
            float x = (__uint_as_float(lo_u) + __uint_as_float(hi_u)) + (Sar[r] + Sbc[c]);
            float e, T;
            asm("ex2.approx.f32 %0, %1;" : "=f"(e) : "f"(x * -1.4426950408889634f));
            asm("rcp.approx.f32 %0, %1;" : "=f"(T) : "f"(1.0f + e));
            if (r == c && dd) T = 0.0f;
            prow[16 * c] = T;
        }
    }
}

extern "C" void kernel_launch(void* const* d_in, const int* in_sizes, int n_in,
                              void* d_out, int out_size)
{
    const float* X     = (const float*)d_in[0];
    const float* W_enc = (const float*)d_in[1];
    const float* b_enc = (const float*)d_in[2];
    const float* W1    = (const float*)d_in[3];
    const float* b1    = (const float*)d_in[4];
    const float* W2    = (const float*)d_in[5];
    const float* b2    = (const float*)d_in[6];
    float* out = (float*)d_out;

    prep_weights<<<9, 256>>>(W_enc, b_enc, W1, b1, W2);
    prep_AB<<<256, 256>>>(X, b2);
    dim3 grid(N_NODES / 64, N_NODES / 64);
    pairwise<<<grid, 256>>>(out);
}

// round 6
// speedup vs baseline: 1.2757x; 1.1291x over previous
#include <cuda_runtime.h>

typedef unsigned long long ull;

#define N_NODES 2048
#define NODE_DIM 128
#define HIDDEN 64

// Scratch (no allocation allowed — device globals)
__device__ __align__(16) float g_HT[HIDDEN * N_NODES];   // [h][node] encoder output, transposed
__device__ __align__(16) ull   g_ABT[64 * N_NODES];      // [h-pair][node]; pairs 0..31 = A(+b1), 32..63 = B
__device__ __align__(16) float g_Sa[N_NODES];            // b2 + sum_h (w/2) a_ih
__device__ __align__(16) float g_Sb[N_NODES];            // sum_h (w/2) b_jh

// ---------------------------------------------------------------------------
// G1: H = X @ W_enc + b_enc, stored transposed g_HT[h][n].
// 128 blocks x 16 nodes. Thread (tx=node lane, p0=col-pair group): 2 pairs.
// ---------------------------------------------------------------------------
__global__ __launch_bounds__(256, 2) void g1_encode(const float* __restrict__ X,
                                                    const float* __restrict__ W_enc,
                                                    const float* __restrict__ b_enc)
{
    __shared__ float Xs[16][129];        // stride 129 -> bank (tx+k), conflict-free
    __shared__ ull   Ws[NODE_DIM][32];   // W_enc col-pairs
    __shared__ ull   bes[32];

    const int t  = threadIdx.x;
    const int n0 = blockIdx.x * 16;

    for (int idx = t; idx < NODE_DIM * 32; idx += 256) {
        int k = idx >> 5, p = idx & 31;
        Ws[k][p] = *(const ull*)&W_enc[k * HIDDEN + 2 * p];
    }
    for (int idx = t; idx < 16 * NODE_DIM; idx += 256) {
        int n = idx >> 7, d = idx & 127;
        Xs[n][d] = X[(n0 + n) * NODE_DIM + d];
    }
    if (t < 32) bes[t] = *(const ull*)&b_enc[2 * t];
    __syncthreads();

    const int tx = t & 15;
    const int p0 = t >> 4;          // 0..15; handles pairs p0 and p0+16

    ull acc0 = 0ull, acc1 = 0ull;
    #pragma unroll 8
    for (int k = 0; k < NODE_DIM; k++) {
        unsigned xu = __float_as_uint(Xs[tx][k]);
        ull x2;
        asm("mov.b64 %0, {%1, %2};" : "=l"(x2) : "r"(xu), "r"(xu));
        ull w0 = Ws[k][p0];
        ull w1 = Ws[k][p0 + 16];
        asm("fma.rn.f32x2 %0, %1, %2, %0;" : "+l"(acc0) : "l"(x2), "l"(w0));
        asm("fma.rn.f32x2 %0, %1, %2, %0;" : "+l"(acc1) : "l"(x2), "l"(w1));
    }

    #pragma unroll
    for (int u = 0; u < 2; u++) {
        const int p = p0 + 16 * u;
        ull a = u ? acc1 : acc0;
        asm("add.rn.f32x2 %0, %0, %1;" : "+l"(a) : "l"(bes[p]));
        unsigned lo_u, hi_u;
        asm("mov.b64 {%0, %1}, %2;" : "=r"(lo_u), "=r"(hi_u) : "l"(a));
        g_HT[(2 * p)     * N_NODES + n0 + tx] = __uint_as_float(lo_u);
        g_HT[(2 * p + 1) * N_NODES + n0 + tx] = __uint_as_float(hi_u);
    }
}

// ---------------------------------------------------------------------------
// G2: AB = H @ [Wa|Wb] (+b1 on A half), transposed store to g_ABT[pair][node].
// Also computes Sa = b2 + sum (w/2)a, Sb = sum (w/2)b via smem reduction.
// 128 blocks x 16 nodes. Thread (tx=node lane, ty=pair group): 4 pairs.
// ---------------------------------------------------------------------------
__global__ __launch_bounds__(256, 2) void g2_project(const float* __restrict__ W1,
                                                     const float* __restrict__ b1,
                                                     const float* __restrict__ W2,
                                                     const float* __restrict__ b2)
{
    __shared__ float Hs[16][65];          // stride 65 -> conflict-free
    __shared__ ull   W1s[128][32];        // full W1 as col-pairs (rows 0..63=Wa, 64..127=Wb)
    __shared__ ull   b1s[32];
    __shared__ float sw2[64];             // 0.5 * W2
    __shared__ float pa[16][17], pb[16][17];

    const int t  = threadIdx.x;
    const int n0 = blockIdx.x * 16;

    for (int idx = t; idx < 128 * 32; idx += 256) {
        int k = idx >> 5, p = idx & 31;
        W1s[k][p] = *(const ull*)&W1[k * HIDDEN + 2 * p];
    }
    for (int idx = t; idx < 64 * 16; idx += 256) {
        int k = idx >> 4, n = idx & 15;
        Hs[n][k] = g_HT[k * N_NODES + n0 + n];
    }
    if (t < 32)       b1s[t]      = *(const ull*)&b1[2 * t];
    else if (t < 96)  sw2[t - 32] = 0.5f * W2[t - 32];
    __syncthreads();

    const int tx = t & 15;
    const int ty = t >> 4;          // 0..15

    ull acc[4];
    #pragma unroll
    for (int u = 0; u < 4; u++) acc[u] = 0ull;

    #pragma unroll 8
    for (int k = 0; k < HIDDEN; k++) {
        unsigned xu = __float_as_uint(Hs[tx][k]);
        ull x2;
        asm("mov.b64 %0, {%1, %2};" : "=l"(x2) : "r"(xu), "r"(xu));
        ull wa0 = W1s[k][ty];
        ull wa1 = W1s[k][ty + 16];
        ull wb0 = W1s[64 + k][ty];
        ull wb1 = W1s[64 + k][ty + 16];
        asm("fma.rn.f32x2 %0, %1, %2, %0;" : "+l"(acc[0]) : "l"(x2), "l"(wa0));
        asm("fma.rn.f32x2 %0, %1, %2, %0;" : "+l"(acc[1]) : "l"(x2), "l"(wa1));
        asm("fma.rn.f32x2 %0, %1, %2, %0;" : "+l"(acc[2]) : "l"(x2), "l"(wb0));
        asm("fma.rn.f32x2 %0, %1, %2, %0;" : "+l"(acc[3]) : "l"(x2), "l"(wb1));
    }

    float pA = 0.f, pB = 0.f;
    #pragma unroll
    for (int u = 0; u < 4; u++) {
        const int pl   = (u & 1) ? ty + 16 : ty;     // pair index within half
        const int pair = (u < 2) ? pl : 32 + pl;     // global pair row in g_ABT
        ull v = acc[u];
        if (u < 2)
            asm("add.rn.f32x2 %0, %0, %1;" : "+l"(v) : "l"(b1s[pl]));
        unsigned lo_u, hi_u;
        asm("mov.b64 {%0, %1}, %2;" : "=r"(lo_u), "=r"(hi_u) : "l"(v));
        float vx = __uint_as_float(lo_u), vy = __uint_as_float(hi_u);
        g_ABT[pair * N_NODES + n0 + tx] = v;
        float contrib = vx * sw2[2 * pl] + vy * sw2[2 * pl + 1];
        if (u < 2) pA += contrib; else pB += contrib;
    }
    pa[ty][tx] = pA;
    pb[ty][tx] = pB;
    __syncthreads();

    if (t < 16) {
        float s = __ldg(b2);
        #pragma unroll
        for (int q = 0; q < 16; q++) s += pa[q][t];
        g_Sa[n0 + t] = s;
    } else if (t < 32) {
        float s = 0.f;
        #pragma unroll
        for (int q = 0; q < 16; q++) s += pb[q][t - 16];
        g_Sb[n0 + t - 16] = s;
    }
}

// ---------------------------------------------------------------------------
// Main: logit_ij = Sa_i + Sb_j + sum_h c_h * |a_ih + b_jh|,  out = sigmoid, diag=0
// (uses w*relu(x) = (w/2)x + (w/2)|x|; separable part precomputed)
// 64x64 tile per block, 256 threads, 4x4 micro-tile, pure-b64 inner loop:
// add.rn.f32x2 -> and.b64 (abs) -> fma.rn.f32x2. Smem tiles [hh][node], stride 65
// -> conflict-free LDS.64 with immediate offsets.
// ---------------------------------------------------------------------------
__global__ __launch_bounds__(256, 2) void pairwise(const float* __restrict__ W2,
                                                   float* __restrict__ out)
{
    __shared__ ull  As[32 * 65];     // [hh][i], 16.6 KB
    __shared__ ull  Bs[32 * 65];
    __shared__ ull  w2s[32];         // c = W2/2, packed pairs
    __shared__ float sSa[64], sSb[64];

    const int t  = threadIdx.x;
    const int i0 = blockIdx.y * 64;
    const int j0 = blockIdx.x * 64;

    for (int idx = t; idx < 2048; idx += 256) {
        int hh = idx >> 6, col = idx & 63;
        As[hh * 65 + col] = g_ABT[hh * N_NODES + i0 + col];
        Bs[hh * 65 + col] = g_ABT[(32 + hh) * N_NODES + j0 + col];
    }
    if (t < 32) {
        ull wp = *(const ull*)&W2[2 * t];
        unsigned lo_u, hi_u;
        asm("mov.b64 {%0, %1}, %2;" : "=r"(lo_u), "=r"(hi_u) : "l"(wp));
        float cx = 0.5f * __uint_as_float(lo_u);
        float cy = 0.5f * __uint_as_float(hi_u);
        asm("mov.b64 %0, {%1, %2};" : "=l"(w2s[t])
            : "r"(__float_as_uint(cx)), "r"(__float_as_uint(cy)));
    }
    else if (t < 96)  sSa[t - 32]  = g_Sa[i0 + t - 32];
    else if (t < 160) sSb[t - 96]  = g_Sb[j0 + t - 96];
    __syncthreads();

    const int tx = t & 15;      // j = j0 + tx + 16c
    const int ty = t >> 4;      // i = i0 + ty + 16r

    ull acc[4][4];
    #pragma unroll
    for (int r = 0; r < 4; r++)
        #pragma unroll
        for (int c = 0; c < 4; c++) acc[r][c] = 0ull;

    #pragma unroll 1
    for (int hh0 = 0; hh0 < 32; hh0 += 16) {
        #pragma unroll
        for (int k = 0; k < 16; k++) {
            const int hh = hh0 + k;
            const ull w2 = w2s[hh];
            ull av[4], bv[4];
            #pragma unroll
            for (int r = 0; r < 4; r++) av[r] = As[hh * 65 + ty + 16 * r];
            #pragma unroll
            for (int c = 0; c < 4; c++) bv[c] = Bs[hh * 65 + tx + 16 * c];
            #pragma unroll
            for (int r = 0; r < 4; r++) {
                #pragma unroll
                for (int c = 0; c < 4; c++) {
                    ull s;
                    asm("add.rn.f32x2 %0, %1, %2;" : "=l"(s) : "l"(av[r]), "l"(bv[c]));
                    asm("and.b64 %0, %0, 0x7FFFFFFF7FFFFFFF;" : "+l"(s));
                    asm("fma.rn.f32x2 %0, %1, %2, %0;" : "+l"(acc[r][c]) : "l"(s), "l"(w2));
                }
            }
        }
    }

    float Sar[4], Sbc[4];
    #pragma unroll
    for (int r = 0; r < 4; r++) Sar[r] = sSa[ty + 16 * r];
    #pragma unroll
    for (int c = 0; c < 4; c++) Sbc[c] = sSb[tx + 16 * c];

    const bool dd = (i0 == j0) && (tx == ty);

    #pragma unroll
    for (int r = 0; r < 4; r++) {
        float* prow = out + (size_t)(i0 + ty + 16 * r) * N_NODES + j0 + tx;
        #pragma unroll
        for (int c = 0; c < 4; c++) {
            unsigned lo_u, hi_u;
            asm("mov.b64 {%0, %1}, %2;" : "=r"(lo_u), "=r"(hi_u) : "l"(acc[r][c]));
            float x = (__uint_as_float(lo_u) + __uint_as_float(hi_u)) + (Sar[r] + Sbc[c]);
            float e, T;
            asm("ex2.approx.f32 %0, %1;" : "=f"(e) : "f"(x * -1.4426950408889634f));
            asm("rcp.approx.f32 %0, %1;" : "=f"(T) : "f"(1.0f + e));
            if (r == c && dd) T = 0.0f;
            prow[16 * c] = T;
        }
    }
}

extern "C" void kernel_launch(void* const* d_in, const int* in_sizes, int n_in,
                              void* d_out, int out_size)
{
    const float* X     = (const float*)d_in[0];
    const float* W_enc = (const float*)d_in[1];
    const float* b_enc = (const float*)d_in[2];
    const float* W1    = (const float*)d_in[3];
    const float* b1    = (const float*)d_in[4];
    const float* W2    = (const float*)d_in[5];
    const float* b2    = (const float*)d_in[6];
    float* out = (float*)d_out;

    g1_encode<<<128, 256>>>(X, W_enc, b_enc);
    g2_project<<<128, 256>>>(W1, b1, W2, b2);
    dim3 grid(N_NODES / 64, N_NODES / 64);
    pairwise<<<grid, 256>>>(W2, out);
}